// round 13
// baseline (speedup 1.0000x reference)
#include <cuda_runtime.h>

#define NB 256
#define NT 1024
#define NI 64
#define NH 25
#define NG 100    // real gate columns
#define NGP 104   // padded gate stride (13*8)
#define NO 64
#define NM (NB*NT)    // 262144 rows
#define NCH 64        // t-chunks of 16 timesteps
#define RD   16       // gx ring slots
#define RPD  12       // gx prefetch distance
#define EP   16       // steps per epoch
#define NEP  (NT/EP)  // 64 epochs
#define SCAN_BLKS 128

// Input gates, T-MAJOR layout: g_gates[(t*NB + b)*NGP + 4k + q] : ~109 MB
static __device__ float g_gates[(size_t)NM * NGP];
// Precomputed W_ih fragments: [kstg 0..7][n 0..103][qid 0..3] = {bh0,bh1,bl0,bl1}
static __device__ uint4 g_wq[8 * NGP * 4];
static __device__ float g_bsum[NGP];
// Per-chunk completion counters (64 gates blocks each)
static __device__ int   g_cnt[NCH];

typedef unsigned long long ull;
typedef unsigned int uint;

__device__ __forceinline__ ull pack2(float a, float b){
    ull r; asm("mov.b64 %0,{%1,%2};" : "=l"(r) : "f"(a), "f"(b)); return r;
}
__device__ __forceinline__ float2 unpack2(ull v){
    float2 r; asm("mov.b64 {%0,%1},%2;" : "=f"(r.x), "=f"(r.y) : "l"(v)); return r;
}
__device__ __forceinline__ ull fma2(ull a, ull b, ull c){
    ull d; asm("fma.rn.f32x2 %0,%1,%2,%3;" : "=l"(d) : "l"(a), "l"(b), "l"(c)); return d;
}
__device__ __forceinline__ ull add2(ull a, ull b){
    ull d; asm("add.rn.f32x2 %0,%1,%2;" : "=l"(d) : "l"(a), "l"(b)); return d;
}
__device__ __forceinline__ float tanha(float x){
    float r; asm("tanh.approx.f32 %0,%1;" : "=f"(r) : "f"(x)); return r;
}
__device__ __forceinline__ float sig_t(float x){
    return fmaf(tanha(0.5f * x), 0.5f, 0.5f);
}
__device__ __forceinline__ unsigned smem_u32(const void* p){
    unsigned a;
    asm("{ .reg .u64 t; cvta.to.shared.u64 t, %1; cvt.u32.u64 %0, t; }"
        : "=r"(a) : "l"(p));
    return a;
}
__device__ __forceinline__ uint to_tf32(float v){
    uint r; asm("cvt.rna.tf32.f32 %0,%1;" : "=r"(r) : "f"(v)); return r;
}
__device__ __forceinline__ void wait_chunk(int c){
    const int* p = &g_cnt[c];
    int v;
    for (;;){
        asm volatile("ld.acquire.gpu.b32 %0,[%1];" : "=r"(v) : "l"(p) : "memory");
        if (v >= 64) break;
        __nanosleep(200);
    }
}

#define MMA_TF32(c, a0,a1,a2,a3, b0,b1)                                   \
    asm volatile("mma.sync.aligned.m16n8k8.row.col.f32.tf32.tf32.f32 "    \
        "{%0,%1,%2,%3}, {%4,%5,%6,%7}, {%8,%9}, {%0,%1,%2,%3};"           \
        : "+f"((c)[0]), "+f"((c)[1]), "+f"((c)[2]), "+f"((c)[3])          \
        : "r"(a0), "r"(a1), "r"(a2), "r"(a3), "r"(b0), "r"(b1))

// shared-memory overlay: scan blocks vs gates blocks
struct ScanS {
    ull ring[2][RD][32][2];     // gx cp.async ring per producer warp (16KB)
    ull hring[2][2*EP][32];     // duplicated h pairs (16KB)
};
struct GateS {
    uint  xs_hi[64][36];        // 9KB
    uint  xs_lo[64][36];        // 9KB
    uint4 bq[4][NGP][4];        // 26.6KB
};
union SU { ScanS s; GateS g; };

// ---------------------------------------------------------------------------
// Kernel 0: precompute W fragments + bias; reset chunk counters.
// ---------------------------------------------------------------------------
__global__ void prep_kernel(const float* __restrict__ W_ih,
                            const float* __restrict__ b_ih,
                            const float* __restrict__ b_hh)
{
    int tid = blockIdx.x * blockDim.x + threadIdx.x;
    const int total = 8 * NGP * 4;
    for (int i = tid; i < total; i += blockDim.x * gridDim.x){
        int qid  = i & 3;
        int n    = (i >> 2) % NGP;
        int kstg = i / (NGP * 4);
        int q = n & 3, kk = n >> 2;
        int k0 = kstg * 8 + qid, k1 = k0 + 4;
        float v0 = (kk < NH) ? W_ih[(q*NH + kk) * NI + k0] : 0.0f;
        float v1 = (kk < NH) ? W_ih[(q*NH + kk) * NI + k1] : 0.0f;
        uint h0 = to_tf32(v0), h1 = to_tf32(v1);
        uint l0 = to_tf32(v0 - __uint_as_float(h0));
        uint l1 = to_tf32(v1 - __uint_as_float(h1));
        g_wq[i] = make_uint4(h0, h1, l0, l1);
    }
    if (tid < NGP){
        int q = tid & 3, kk = tid >> 2;
        g_bsum[tid] = (kk < NH) ? (b_ih[q*NH + kk] + b_hh[q*NH + kk]) : 0.0f;
    }
    if (tid < NCH) g_cnt[tid] = 0;
}

// ---------------------------------------------------------------------------
// Gates producer block: TF32 MMA for tile g (one timestep t = g>>2,
// batches b0..b0+63, b0 = (g&3)*64). Signals g_cnt[g>>6] when done.
// ---------------------------------------------------------------------------
__device__ __forceinline__ void gates_part(const float* __restrict__ x,
                                           GateS& S, int g)
{
    const int tid  = threadIdx.x;
    const int lane = tid & 31;
    const int wid  = tid >> 5;
    const int grp  = lane >> 2;
    const int qid  = lane & 3;
    const int t    = g >> 2;
    const int b0   = (g & 3) * 64;

    float acc[13][4];
    #pragma unroll
    for (int nt = 0; nt < 13; nt++)
        #pragma unroll
        for (int i = 0; i < 4; i++) acc[nt][i] = 0.0f;

    const unsigned bq_s = smem_u32(&S.bq[0][0][0]);

    for (int pass = 0; pass < 2; pass++){
        const int ks = pass * 32;
        __syncthreads();

        {
            const char* src = reinterpret_cast<const char*>(g_wq)
                              + (size_t)pass * 4 * NGP * 4 * 16;
            #pragma unroll
            for (int i = 0; i < 13; i++){
                int off = (tid + i * 128) * 16;
                asm volatile("cp.async.ca.shared.global [%0], [%1], 16;"
                             :: "r"(bq_s + off), "l"(src + off) : "memory");
            }
            asm volatile("cp.async.commit_group;" ::: "memory");
        }

        #pragma unroll
        for (int i = 0; i < 4; i++){
            int idx = tid + i * 128;
            int r = idx >> 3, f4 = idx & 7;
            float4 v = *reinterpret_cast<const float4*>(
                x + ((size_t)(b0 + r) * NT + t) * NI + ks + f4 * 4);
            uint4 hb, lb;
            hb.x = to_tf32(v.x); lb.x = to_tf32(v.x - __uint_as_float(hb.x));
            hb.y = to_tf32(v.y); lb.y = to_tf32(v.y - __uint_as_float(hb.y));
            hb.z = to_tf32(v.z); lb.z = to_tf32(v.z - __uint_as_float(hb.z));
            hb.w = to_tf32(v.w); lb.w = to_tf32(v.w - __uint_as_float(hb.w));
            *reinterpret_cast<uint4*>(&S.xs_hi[r][f4 * 4]) = hb;
            *reinterpret_cast<uint4*>(&S.xs_lo[r][f4 * 4]) = lb;
        }
        asm volatile("cp.async.wait_group 0;" ::: "memory");
        __syncthreads();

        #pragma unroll
        for (int kst = 0; kst < 4; kst++){
            const int r0 = wid * 16 + grp;
            const int c0 = kst * 8 + qid;
            uint ah0 = S.xs_hi[r0][c0],   ah1 = S.xs_hi[r0+8][c0];
            uint ah2 = S.xs_hi[r0][c0+4], ah3 = S.xs_hi[r0+8][c0+4];
            uint al0 = S.xs_lo[r0][c0],   al1 = S.xs_lo[r0+8][c0];
            uint al2 = S.xs_lo[r0][c0+4], al3 = S.xs_lo[r0+8][c0+4];
            #pragma unroll
            for (int nt = 0; nt < 13; nt++){
                uint4 bv = S.bq[kst][nt * 8 + grp][qid];
                MMA_TF32(acc[nt], ah0, ah1, ah2, ah3, bv.x, bv.y);
                MMA_TF32(acc[nt], al0, al1, al2, al3, bv.x, bv.y);
                MMA_TF32(acc[nt], ah0, ah1, ah2, ah3, bv.z, bv.w);
            }
        }
    }

    const size_t rg = (size_t)t * NB + b0 + wid * 16 + grp;
    #pragma unroll
    for (int nt = 0; nt < 13; nt++){
        int col = nt * 8 + 2 * qid;
        float2 bsv = *reinterpret_cast<const float2*>(&g_bsum[col]);
        float2 v0 = { acc[nt][0] + bsv.x, acc[nt][1] + bsv.y };
        float2 v1 = { acc[nt][2] + bsv.x, acc[nt][3] + bsv.y };
        *reinterpret_cast<float2*>(&g_gates[ rg      * NGP + col]) = v0;
        *reinterpret_cast<float2*>(&g_gates[(rg + 8) * NGP + col]) = v1;
    }

    __threadfence();
    __syncthreads();
    if (tid == 0){
        asm volatile("fence.acq_rel.gpu;" ::: "memory");
        atomicAdd(&g_cnt[g >> 6], 1);
    }
}

// ---------------------------------------------------------------------------
// Fused kernel: blocks 0..127 = scan(+FC helper warps), rest = gates tiles.
// Scan epochs gated on chunk counters; chunk rate > epoch rate -> no stalls
// after startup. T-step stride in g_gates is NB*NGP floats.
// ---------------------------------------------------------------------------
__global__ void __launch_bounds__(128, 1) fused_kernel(
    const float* __restrict__ x,
    const float* __restrict__ W_hh, const float* __restrict__ W_fc,
    const float* __restrict__ b_fc, float* __restrict__ out)
{
    __shared__ SU su;

    if (blockIdx.x >= SCAN_BLKS){
        gates_part(x, su.g, blockIdx.x - SCAN_BLKS);
        return;
    }

    const int tid  = threadIdx.x;
    const int lane = tid & 31;
    const int wrp  = tid >> 5;            // 0..3
    const int bw   = wrp & 1;
    const int b    = blockIdx.x * 2 + bw;
    const bool producer = (wrp < 2);
    const size_t TSTR = (size_t)NB * NGP; // floats per timestep

    // role-specific setup
    int k = 0, o0 = 0;
    ull w_if[NH], w_go[NH], wf[NH];
    ull bfc = 0ull;
    const float* gxb = nullptr;
    float* ob = nullptr;
    if (producer){
        k = (lane < NH) ? lane : NH - 1;
        gxb = g_gates + (size_t)b * NGP + 4 * k;
        #pragma unroll
        for (int kk = 0; kk < NH; kk++){
            w_if[kk] = pack2(__ldg(W_hh + (     k) * NH + kk), __ldg(W_hh + (NH  + k) * NH + kk));
            w_go[kk] = pack2(__ldg(W_hh + (2*NH+k) * NH + kk), __ldg(W_hh + (3*NH+k) * NH + kk));
        }
    } else {
        o0 = 2 * lane;
        ob = out + (size_t)b * NT * NO + o0;
        #pragma unroll
        for (int kk = 0; kk < NH; kk++)
            wf[kk] = pack2(__ldg(W_fc + o0 * NH + kk), __ldg(W_fc + (o0+1) * NH + kk));
        bfc = pack2(__ldg(b_fc + o0), __ldg(b_fc + o0 + 1));
    }

    const unsigned rbase = smem_u32(&su.s.ring[bw][0][lane][0]);
    #define SLOT_ADDR(s) (rbase + (unsigned)(s) * (32u * 16u))

    // startup: chunk 0 must exist before prologue prefetch (t=0..11)
    if (tid == 0) wait_chunk(0);
    __syncthreads();

    if (producer){
        #pragma unroll
        for (int d = 0; d < RPD; d++){
            asm volatile("cp.async.ca.shared.global [%0], [%1], 16;"
                         :: "r"(SLOT_ADDR(d)), "l"(gxb + (size_t)d * TSTR) : "memory");
            asm volatile("cp.async.commit_group;" ::: "memory");
        }
    }

    float h = 0.0f, c = 0.0f;

    for (int e = 0; e <= NEP; e++){
        // gate prefetch range of epoch e: chunk e+1 must be complete
        if (e < NEP && tid == 0){
            int ch = e + 1; if (ch > NCH - 1) ch = NCH - 1;
            wait_chunk(ch);
        }
        __syncthreads();   // barrier A

        if (producer){
            if (e < NEP){
                #pragma unroll 4
                for (int u = 0; u < EP; u++){
                    const int t = e * EP + u;
                    asm volatile("cp.async.wait_group 11;" ::: "memory");
                    float4 pv = *reinterpret_cast<const float4*>(
                                    &su.s.ring[bw][t & (RD-1)][lane][0]);

                    {   // refill slot t+RPD
                        unsigned pred = (t + RPD < NT) ? 1u : 0u;
                        asm volatile(
                            "{ .reg .pred q; setp.ne.u32 q, %0, 0;"
                            "  @q cp.async.ca.shared.global [%1], [%2], 16; }"
                            :: "r"(pred), "r"(SLOT_ADDR((t + RPD) & (RD-1))),
                               "l"(gxb + (size_t)(t + RPD) * TSTR) : "memory");
                        asm volatile("cp.async.commit_group;" ::: "memory");
                    }

                    ull aif[4], ago[4];
                    aif[0] = pack2(pv.x, pv.y); aif[1] = 0ull; aif[2] = 0ull; aif[3] = 0ull;
                    ago[0] = pack2(pv.z, pv.w); ago[1] = 0ull; ago[2] = 0ull; ago[3] = 0ull;

                    #pragma unroll
                    for (int kk = 0; kk < NH; kk++){
                        float hv = __shfl_sync(0xffffffffu, h, kk);
                        ull hd = pack2(hv, hv);
                        aif[kk & 3] = fma2(hd, w_if[kk], aif[kk & 3]);
                        ago[kk & 3] = fma2(hd, w_go[kk], ago[kk & 3]);
                    }

                    float2 gif = unpack2(add2(add2(aif[0], aif[1]), add2(aif[2], aif[3])));
                    float2 ggo = unpack2(add2(add2(ago[0], ago[1]), add2(ago[2], ago[3])));
                    float iv = sig_t(gif.x);
                    float fv = sig_t(gif.y);
                    float gv = tanha(ggo.x);
                    float ov = sig_t(ggo.y);
                    c = fv * c + iv * gv;
                    h = ov * tanha(c);

                    su.s.hring[bw][t & (2*EP - 1)][lane] = pack2(h, h);
                }
            }
        } else {
            if (e > 0){
                #pragma unroll 4
                for (int u = 0; u < EP; u++){
                    const int t = (e - 1) * EP + u;
                    ull a0 = bfc, a1 = 0ull;
                    #pragma unroll
                    for (int kk = 0; kk < NH; kk++){
                        ull hd = su.s.hring[bw][t & (2*EP - 1)][kk];
                        if (kk & 1) a1 = fma2(hd, wf[kk], a1);
                        else        a0 = fma2(hd, wf[kk], a0);
                    }
                    *reinterpret_cast<float2*>(ob + (size_t)t * NO) =
                        unpack2(add2(a0, a1));
                }
            }
        }
        __syncthreads();   // barrier B: publish epoch e half
    }
    #undef SLOT_ADDR
}

extern "C" void kernel_launch(void* const* d_in, const int* in_sizes, int n_in,
                              void* d_out, int out_size)
{
    (void)in_sizes; (void)n_in; (void)out_size;
    const float* x    = (const float*)d_in[0];
    const float* W_ih = (const float*)d_in[1];
    const float* W_hh = (const float*)d_in[2];
    const float* b_ih = (const float*)d_in[3];
    const float* b_hh = (const float*)d_in[4];
    const float* W_fc = (const float*)d_in[5];
    const float* b_fc = (const float*)d_in[6];
    float* out = (float*)d_out;

    prep_kernel<<<8, 256>>>(W_ih, b_ih, b_hh);
    fused_kernel<<<SCAN_BLKS + NM / 64, 128>>>(x, W_hh, W_fc, b_fc, out);
}